// round 1
// baseline (speedup 1.0000x reference)
#include <cuda_runtime.h>
#include <math.h>

#define Bn  8
#define SQ  128
#define SK  128
#define IVD 32
#define DIM 32
#define EV  64
#define Hh  8
#define NH  128
#define DKd 8

// scratch (allocation-free rule: device globals)
__device__ float g_q[Bn*SQ*EV];
__device__ float g_k[Bn*SK*EV];
__device__ float g_x[Bn*SQ*Hh*DIM];

// ---------------------------------------------------------------------------
// K1: qe/ke = tanh(X@w1+b1)@w2 ; then q = qe@wq+bq (or k = ke@wk+bk)
// one block per row (2048 rows total), 128 threads
// ---------------------------------------------------------------------------
__global__ void __launch_bounds__(128) proj_kernel(
    const float* __restrict__ qv, const float* __restrict__ kv,
    const float* __restrict__ w1, const float* __restrict__ b1,
    const float* __restrict__ w2,
    const float* __restrict__ wq, const float* __restrict__ bq,
    const float* __restrict__ wk, const float* __restrict__ bk)
{
    __shared__ float xs[IVD];
    __shared__ float hs[NH];
    __shared__ float es[EV];

    int row = blockIdx.x;               // 0..2047
    bool isQ = row < Bn*SQ;
    int r = isQ ? row : row - Bn*SQ;
    const float* xin = isQ ? qv : kv;
    const float* wp  = isQ ? wq : wk;
    const float* bp  = isQ ? bq : bk;
    float* outp      = isQ ? g_q : g_k;

    int t = threadIdx.x;
    if (t < IVD) xs[t] = xin[r*IVD + t];
    __syncthreads();

    // hidden: 128 outputs, 32 MACs each
    {
        float acc = b1[t];
        #pragma unroll
        for (int i = 0; i < IVD; i++) acc = fmaf(xs[i], w1[i*NH + t], acc);
        hs[t] = tanhf(acc);
    }
    __syncthreads();

    // embed: 64 outputs, 128 MACs each
    if (t < EV) {
        float a = 0.f;
        #pragma unroll 8
        for (int p = 0; p < NH; p++) a = fmaf(hs[p], w2[p*EV + t], a);
        es[t] = a;
    }
    __syncthreads();

    // q/k projection: 64 outputs, 64 MACs each
    if (t < EV) {
        float a = bp[t];
        #pragma unroll 8
        for (int p = 0; p < EV; p++) a = fmaf(es[p], wp[p*EV + t], a);
        outp[r*EV + t] = a;
    }
}

// ---------------------------------------------------------------------------
// K2: masked-softmax attention.
// out[b,h,q,d] = sum_k m[b,k,d]*e_k*v[b,k,d] / sum_k m[b,k,d]*e_k
// with e_k = exp((s_k - max_k s_k)/sqrt(DK)) ; masked terms underflow to 0
// exactly as in the fp32 reference.
// grid = B*H*2 (q split in halves), 64 threads; thread = one q row.
// ---------------------------------------------------------------------------
__global__ void __launch_bounds__(64) attn_kernel(
    const float* __restrict__ value, const int* __restrict__ mask)
{
    __shared__ float qs[64*DKd];
    __shared__ float ks[SK*DKd];
    __shared__ float mv[SK*DIM];   // mask * value
    __shared__ float mf[SK*DIM];   // mask as float

    int blk  = blockIdx.x;         // b*16 + h*2 + half
    int half = blk & 1;
    int h    = (blk >> 1) & 7;
    int b    = blk >> 4;
    int t    = threadIdx.x;        // 0..63
    int q    = half*64 + t;

    #pragma unroll
    for (int j = 0; j < DKd; j++)
        qs[t*DKd + j] = g_q[(b*SQ + q)*EV + h*DKd + j];

    for (int kk = t; kk < SK; kk += 64) {
        #pragma unroll
        for (int j = 0; j < DKd; j++)
            ks[kk*DKd + j] = g_k[(b*SK + kk)*EV + h*DKd + j];
        #pragma unroll
        for (int d = 0; d < DIM; d++) {
            int   m = mask [(b*SK + kk)*DIM + d];
            float v = value[(b*SK + kk)*DIM + d];
            mv[kk*DIM + d] = m ? v   : 0.f;
            mf[kk*DIM + d] = m ? 1.f : 0.f;
        }
    }
    __syncthreads();

    float qr[DKd];
    #pragma unroll
    for (int j = 0; j < DKd; j++) qr[j] = qs[t*DKd + j];

    const float scale = 0.35355339059327373f;  // 1/sqrt(8)

    // pass 1: row max of raw scores (scale > 0, so max commutes with scale)
    float mx = -1e30f;
    #pragma unroll 4
    for (int k = 0; k < SK; k++) {
        float s = 0.f;
        #pragma unroll
        for (int j = 0; j < DKd; j++) s = fmaf(qr[j], ks[k*DKd + j], s);
        mx = fmaxf(mx, s);
    }
    mx *= scale;

    // pass 2: recompute score, exp, accumulate masked num/den over d
    float num[DIM], den[DIM];
    #pragma unroll
    for (int d = 0; d < DIM; d++) { num[d] = 0.f; den[d] = 0.f; }

    for (int k = 0; k < SK; k++) {
        float s = 0.f;
        #pragma unroll
        for (int j = 0; j < DKd; j++) s = fmaf(qr[j], ks[k*DKd + j], s);
        float e = __expf(fmaf(s, scale, -mx));
        const float4* mv4 = (const float4*)&mv[k*DIM];
        const float4* mf4 = (const float4*)&mf[k*DIM];
        #pragma unroll
        for (int d4 = 0; d4 < DIM/4; d4++) {
            float4 a = mv4[d4], c = mf4[d4];
            num[d4*4+0] = fmaf(e, a.x, num[d4*4+0]);
            num[d4*4+1] = fmaf(e, a.y, num[d4*4+1]);
            num[d4*4+2] = fmaf(e, a.z, num[d4*4+2]);
            num[d4*4+3] = fmaf(e, a.w, num[d4*4+3]);
            den[d4*4+0] = fmaf(e, c.x, den[d4*4+0]);
            den[d4*4+1] = fmaf(e, c.y, den[d4*4+1]);
            den[d4*4+2] = fmaf(e, c.z, den[d4*4+2]);
            den[d4*4+3] = fmaf(e, c.w, den[d4*4+3]);
        }
    }

    #pragma unroll
    for (int d = 0; d < DIM; d++)
        g_x[(b*SQ + q)*(Hh*DIM) + h*DIM + d] = num[d] / den[d];
}

// ---------------------------------------------------------------------------
// K3: y = x @ wo + bo  (x: [1024, 256], wo: [256,128])
// one block per row, 128 threads (one output each)
// ---------------------------------------------------------------------------
__global__ void __launch_bounds__(128) out_kernel(
    const float* __restrict__ wo, const float* __restrict__ bo,
    float* __restrict__ out)
{
    __shared__ float xs[Hh*DIM];
    int row = blockIdx.x;
    int t = threadIdx.x;
    xs[t]       = g_x[row*256 + t];
    xs[t + 128] = g_x[row*256 + t + 128];
    __syncthreads();
    float acc = bo[t];
    #pragma unroll 8
    for (int p = 0; p < 256; p++) acc = fmaf(xs[p], wo[p*NH + t], acc);
    out[row*NH + t] = acc;
}

// ---------------------------------------------------------------------------
// K4: query_data = relu(LN(impute@wd1+bd1)) @ wd2 + bd2
// one block per row, 128 threads
// ---------------------------------------------------------------------------
__global__ void __launch_bounds__(128) mlp_kernel(
    const float* __restrict__ imp,
    const float* __restrict__ wd1, const float* __restrict__ bd1,
    const float* __restrict__ lng, const float* __restrict__ lnb,
    const float* __restrict__ wd2, const float* __restrict__ bd2,
    float* __restrict__ out)
{
    __shared__ float xs[16];
    __shared__ float hs[NH];
    __shared__ float red[8];

    int row = blockIdx.x;
    int t = threadIdx.x;
    if (t < 16) xs[t] = imp[row*16 + t];
    __syncthreads();

    float a = bd1[t];
    #pragma unroll
    for (int i = 0; i < 16; i++) a = fmaf(xs[i], wd1[i*NH + t], a);

    // mean / var over 128 via warp shuffles + smem
    float s = a, s2 = a*a;
    #pragma unroll
    for (int off = 16; off > 0; off >>= 1) {
        s  += __shfl_xor_sync(0xffffffff, s,  off);
        s2 += __shfl_xor_sync(0xffffffff, s2, off);
    }
    int wid = t >> 5, lane = t & 31;
    if (lane == 0) { red[wid] = s; red[wid + 4] = s2; }
    __syncthreads();
    float S  = red[0] + red[1] + red[2] + red[3];
    float S2 = red[4] + red[5] + red[6] + red[7];
    float mu  = S * (1.f/128.f);
    float var = S2 * (1.f/128.f) - mu*mu;

    float ln = (a - mu) * rsqrtf(var + 1e-5f) * lng[t] + lnb[t];
    hs[t] = fmaxf(ln, 0.f);
    __syncthreads();

    float acc = bd2[t];
    #pragma unroll 8
    for (int p = 0; p < NH; p++) acc = fmaf(hs[p], wd2[p*NH + t], acc);
    out[row*NH + t] = acc;
}

// ---------------------------------------------------------------------------
extern "C" void kernel_launch(void* const* d_in, const int* in_sizes, int n_in,
                              void* d_out, int out_size)
{
    // Disambiguate input ordering: dict order has emb_mask (32768 elems) at
    // index 4; function-parameter order has w1 (4096 elems) there.
    bool dictOrder = (in_sizes[4] == Bn*SK*DIM);

    const float *qv, *kv, *val, *imp, *w1, *b1, *w2, *wq, *bq, *wk, *bk,
                *wo, *bo, *wd1, *bd1, *lng, *lnb, *wd2, *bd2;
    const int* mask;

    if (dictOrder) {
        qv  = (const float*)d_in[0];  kv  = (const float*)d_in[1];
        val = (const float*)d_in[2];  imp = (const float*)d_in[3];
        mask= (const int*)  d_in[4];
        w1  = (const float*)d_in[5];  b1  = (const float*)d_in[6];
        w2  = (const float*)d_in[7];
        wq  = (const float*)d_in[8];  bq  = (const float*)d_in[9];
        wk  = (const float*)d_in[10]; bk  = (const float*)d_in[11];
        wo  = (const float*)d_in[12]; bo  = (const float*)d_in[13];
        wd1 = (const float*)d_in[14]; bd1 = (const float*)d_in[15];
        lng = (const float*)d_in[16]; lnb = (const float*)d_in[17];
        wd2 = (const float*)d_in[18]; bd2 = (const float*)d_in[19];
    } else {
        qv  = (const float*)d_in[0];  kv  = (const float*)d_in[1];
        val = (const float*)d_in[2];  imp = (const float*)d_in[3];
        w1  = (const float*)d_in[4];  b1  = (const float*)d_in[5];
        w2  = (const float*)d_in[6];
        wq  = (const float*)d_in[7];  bq  = (const float*)d_in[8];
        wk  = (const float*)d_in[9];  bk  = (const float*)d_in[10];
        wo  = (const float*)d_in[11]; bo  = (const float*)d_in[12];
        wd1 = (const float*)d_in[13]; bd1 = (const float*)d_in[14];
        lng = (const float*)d_in[15]; lnb = (const float*)d_in[16];
        wd2 = (const float*)d_in[17]; bd2 = (const float*)d_in[18];
        mask= (const int*)  d_in[19];
    }

    float* y  = (float*)d_out;                       // [8,128,128]
    float* qd = (float*)d_out + Bn*SQ*NH;            // [8,128,128]

    proj_kernel<<<2*Bn*SQ, 128>>>(qv, kv, w1, b1, w2, wq, bq, wk, bk);
    attn_kernel<<<Bn*Hh*2, 64>>>(val, mask);
    out_kernel<<<Bn*SQ, 128>>>(wo, bo, y);
    mlp_kernel<<<Bn*SQ, 128>>>(imp, wd1, bd1, lng, lnb, wd2, bd2, qd);
}

// round 2
// speedup vs baseline: 1.1164x; 1.1164x over previous
#include <cuda_runtime.h>
#include <math.h>

#define Bn  8
#define SQ  128
#define SK  128
#define IVD 32
#define DIM 32
#define EV  64
#define Hh  8
#define NH  128
#define DKd 8

// scratch (allocation-free rule: device globals)
__device__ float g_q[Bn*SQ*EV];
__device__ float g_k[Bn*SK*EV];
__device__ float g_x[Bn*SQ*Hh*DIM];

// ---------------------------------------------------------------------------
// Fused kernel 1:
//   blocks [0,512):   proj — 4 rows/block of the 2048-row combined q/k set:
//                     e = tanh(X@w1+b1)@w2 ; q/k = e@{wq,wk}+{bq,bk}
//   blocks [512,640): impute MLP — 8 rows/block:
//                     qd = relu(LN(imp@wd1+bd1)) @ wd2 + bd2
// 128 threads. Row batching gives 4-8 independent accumulators per thread
// (ILP) and amortizes each weight load over all rows.
// ---------------------------------------------------------------------------
__global__ void __launch_bounds__(128) fused1_kernel(
    const float* __restrict__ qv, const float* __restrict__ kv,
    const float* __restrict__ w1, const float* __restrict__ b1,
    const float* __restrict__ w2,
    const float* __restrict__ wq, const float* __restrict__ bq,
    const float* __restrict__ wk, const float* __restrict__ bk,
    const float* __restrict__ imp,
    const float* __restrict__ wd1, const float* __restrict__ bd1,
    const float* __restrict__ lng, const float* __restrict__ lnb,
    const float* __restrict__ wd2, const float* __restrict__ bd2,
    float* __restrict__ qd_out)
{
    int t = threadIdx.x;

    if (blockIdx.x < 512) {
        // ---------------- proj part ----------------
        __shared__ float xs[4*IVD];     // 4 input rows
        __shared__ float hsm[4*NH];     // hidden
        __shared__ float esm[4*EV];     // embed

        int r0 = blockIdx.x * 4;            // global row in [0,2048)
        bool isQ = r0 < Bn*SQ;
        int rr0 = isQ ? r0 : r0 - Bn*SQ;
        const float* xin = isQ ? qv : kv;
        const float* wp  = isQ ? wq : wk;
        const float* bp  = isQ ? bq : bk;
        float* outp      = isQ ? g_q : g_k;

        xs[t] = xin[rr0*IVD + t];           // 128 floats = 4 rows x 32
        __syncthreads();

        // hidden: col t for 4 rows
        {
            float bb = b1[t];
            float a0 = bb, a1 = bb, a2 = bb, a3 = bb;
            #pragma unroll
            for (int i = 0; i < IVD; i++) {
                float w = w1[i*NH + t];
                a0 = fmaf(xs[0*IVD+i], w, a0);
                a1 = fmaf(xs[1*IVD+i], w, a1);
                a2 = fmaf(xs[2*IVD+i], w, a2);
                a3 = fmaf(xs[3*IVD+i], w, a3);
            }
            hsm[0*NH+t] = tanhf(a0);
            hsm[1*NH+t] = tanhf(a1);
            hsm[2*NH+t] = tanhf(a2);
            hsm[3*NH+t] = tanhf(a3);
        }
        __syncthreads();

        int c  = t & 63;
        int rp = t >> 6;   // thread covers rows rp and rp+2

        // embed: col c for 2 rows
        {
            float a0 = 0.f, a1 = 0.f;
            #pragma unroll 8
            for (int p = 0; p < NH; p++) {
                float w = w2[p*EV + c];
                a0 = fmaf(hsm[rp*NH + p],     w, a0);
                a1 = fmaf(hsm[(rp+2)*NH + p], w, a1);
            }
            esm[rp*EV + c]     = a0;
            esm[(rp+2)*EV + c] = a1;
        }
        __syncthreads();

        // q/k projection: col c for 2 rows
        {
            float bb = bp[c];
            float a0 = bb, a1 = bb;
            #pragma unroll 8
            for (int p = 0; p < EV; p++) {
                float w = wp[p*EV + c];
                a0 = fmaf(esm[rp*EV + p],     w, a0);
                a1 = fmaf(esm[(rp+2)*EV + p], w, a1);
            }
            outp[(rr0+rp)*EV + c]   = a0;
            outp[(rr0+rp+2)*EV + c] = a1;
        }
    } else {
        // ---------------- impute MLP part (8 rows/block) ----------------
        __shared__ float xi[8*16];
        __shared__ float ht[NH*8];      // hidden, transposed [p][r]
        __shared__ float redS[4*8], redQ[4*8];

        int row0 = (blockIdx.x - 512) * 8;
        xi[t] = imp[row0*16 + t];       // 128 floats = 8 rows x 16
        __syncthreads();

        // GEMM1: col t for 8 rows
        float a[8];
        {
            float bb = bd1[t];
            #pragma unroll
            for (int r = 0; r < 8; r++) a[r] = bb;
            #pragma unroll
            for (int i = 0; i < 16; i++) {
                float w = wd1[i*NH + t];
                #pragma unroll
                for (int r = 0; r < 8; r++) a[r] = fmaf(xi[r*16+i], w, a[r]);
            }
        }

        // per-row mean/var across 128 threads
        float ss[8], qq[8];
        #pragma unroll
        for (int r = 0; r < 8; r++) { ss[r] = a[r]; qq[r] = a[r]*a[r]; }
        #pragma unroll
        for (int off = 16; off > 0; off >>= 1) {
            #pragma unroll
            for (int r = 0; r < 8; r++) {
                ss[r] += __shfl_xor_sync(0xffffffff, ss[r], off);
                qq[r] += __shfl_xor_sync(0xffffffff, qq[r], off);
            }
        }
        int wid = t >> 5, lane = t & 31;
        if (lane == 0) {
            #pragma unroll
            for (int r = 0; r < 8; r++) { redS[wid*8+r] = ss[r]; redQ[wid*8+r] = qq[r]; }
        }
        __syncthreads();

        float g = lng[t], be = lnb[t];
        #pragma unroll
        for (int r = 0; r < 8; r++) {
            float S = redS[r] + redS[8+r] + redS[16+r] + redS[24+r];
            float Q = redQ[r] + redQ[8+r] + redQ[16+r] + redQ[24+r];
            float mu  = S * (1.f/128.f);
            float var = Q * (1.f/128.f) - mu*mu;
            float ln = (a[r] - mu) * rsqrtf(var + 1e-5f) * g + be;
            ht[t*8 + r] = fmaxf(ln, 0.f);
        }
        __syncthreads();

        // GEMM2: col t for 8 rows, transposed smem reads (float4 broadcast)
        float acc[8];
        {
            float bb = bd2[t];
            #pragma unroll
            for (int r = 0; r < 8; r++) acc[r] = bb;
            const float4* h4 = (const float4*)ht;
            #pragma unroll 4
            for (int p = 0; p < NH; p++) {
                float w = wd2[p*NH + t];
                float4 x0 = h4[p*2], x1 = h4[p*2+1];
                acc[0] = fmaf(x0.x, w, acc[0]);
                acc[1] = fmaf(x0.y, w, acc[1]);
                acc[2] = fmaf(x0.z, w, acc[2]);
                acc[3] = fmaf(x0.w, w, acc[3]);
                acc[4] = fmaf(x1.x, w, acc[4]);
                acc[5] = fmaf(x1.y, w, acc[5]);
                acc[6] = fmaf(x1.z, w, acc[6]);
                acc[7] = fmaf(x1.w, w, acc[7]);
            }
        }
        #pragma unroll
        for (int r = 0; r < 8; r++) qd_out[(row0+r)*NH + t] = acc[r];
    }
}

// ---------------------------------------------------------------------------
// K2: masked-softmax attention.
// out[b,h,q,d] = sum_k m[b,k,d]*e_k*v[b,k,d] / sum_k m[b,k,d]*e_k
// e_k = exp((s_k - max)/sqrt(DK)); masked logits underflow to exactly 0.
// grid = B*H*8 (16-q tiles), 128 threads.
// Phase A: thread=(q, k-octile): scores once, shfl max, exp -> smem.
// Phase B: thread=(q, d-octile): 4 num + 4 den accumulators, float4 smem.
// ---------------------------------------------------------------------------
__global__ void __launch_bounds__(128) attn_kernel(
    const float* __restrict__ value, const int* __restrict__ mask)
{
    __shared__ float qs[16*DKd];      // 0.5 KB
    __shared__ float ks[SK*DKd];      // 4 KB
    __shared__ float mv[SK*DIM];      // 16 KB  mask*value
    __shared__ float mf[SK*DIM];      // 16 KB  mask as float
    __shared__ float es[16*SK];       // 8 KB   exp weights

    int blk = blockIdx.x;             // b*64 + h*8 + qg
    int qg  = blk & 7;
    int h   = (blk >> 3) & 7;
    int b   = blk >> 6;
    int q0  = qg * 16;
    int t   = threadIdx.x;

    // loads
    qs[t] = g_q[(b*SQ + q0 + (t>>3))*EV + h*DKd + (t&7)];
    #pragma unroll
    for (int j = 0; j < 8; j++) {
        int idx = t + j*128;          // over 1024 = 128k x 8d
        ks[idx] = g_k[(b*SK + (idx>>3))*EV + h*DKd + (idx&7)];
    }
    {
        const float4* v4 = (const float4*)(value + b*SK*DIM);
        const int4*   m4 = (const int4*)  (mask  + b*SK*DIM);
        float4* mv4 = (float4*)mv;
        float4* mf4 = (float4*)mf;
        #pragma unroll
        for (int j = 0; j < 8; j++) {
            int idx = t + j*128;      // over 1024 float4s
            int4 mm = m4[idx]; float4 vv = v4[idx];
            float4 av, af;
            av.x = mm.x ? vv.x : 0.f;  af.x = mm.x ? 1.f : 0.f;
            av.y = mm.y ? vv.y : 0.f;  af.y = mm.y ? 1.f : 0.f;
            av.z = mm.z ? vv.z : 0.f;  af.z = mm.z ? 1.f : 0.f;
            av.w = mm.w ? vv.w : 0.f;  af.w = mm.w ? 1.f : 0.f;
            mv4[idx] = av; mf4[idx] = af;
        }
    }
    __syncthreads();

    const float scale = 0.35355339059327373f;   // 1/sqrt(8)

    // ---------------- phase A: scores + softmax weights ----------------
    {
        int q  = t >> 3;              // 0..15
        int kq = t & 7;               // k range [kq*16, kq*16+16)
        float qr[DKd];
        #pragma unroll
        for (int j = 0; j < DKd; j++) qr[j] = qs[q*DKd + j];

        float s[16];
        int kbase = kq * 16;
        #pragma unroll
        for (int i = 0; i < 16; i++) {
            const float4* kp = (const float4*)&ks[(kbase+i)*DKd];
            float4 k0 = kp[0], k1 = kp[1];
            float acc = qr[0]*k0.x;
            acc = fmaf(qr[1], k0.y, acc);
            acc = fmaf(qr[2], k0.z, acc);
            acc = fmaf(qr[3], k0.w, acc);
            acc = fmaf(qr[4], k1.x, acc);
            acc = fmaf(qr[5], k1.y, acc);
            acc = fmaf(qr[6], k1.z, acc);
            acc = fmaf(qr[7], k1.w, acc);
            s[i] = acc;
        }
        float mx = s[0];
        #pragma unroll
        for (int i = 1; i < 16; i++) mx = fmaxf(mx, s[i]);
        mx = fmaxf(mx, __shfl_xor_sync(0xffffffff, mx, 1));
        mx = fmaxf(mx, __shfl_xor_sync(0xffffffff, mx, 2));
        mx = fmaxf(mx, __shfl_xor_sync(0xffffffff, mx, 4));
        float msc = mx * scale;
        #pragma unroll
        for (int i = 0; i < 16; i++)
            es[q*SK + kbase + i] = __expf(fmaf(s[i], scale, -msc));
    }
    __syncthreads();

    // ---------------- phase B: masked weighted accumulation ----------------
    {
        int q  = t >> 3;              // 0..15
        int dq = t & 7;               // d range [dq*4, dq*4+4)
        float n0=0.f, n1=0.f, n2=0.f, n3=0.f;
        float d0=0.f, d1=0.f, d2=0.f, d3=0.f;
        const float4* mv4 = (const float4*)mv;
        const float4* mf4 = (const float4*)mf;
        const float*  ep  = &es[q*SK];
        #pragma unroll 4
        for (int k = 0; k < SK; k++) {
            float e = ep[k];
            float4 v = mv4[k*8 + dq];
            float4 m = mf4[k*8 + dq];
            n0 = fmaf(e, v.x, n0);  d0 = fmaf(e, m.x, d0);
            n1 = fmaf(e, v.y, n1);  d1 = fmaf(e, m.y, d1);
            n2 = fmaf(e, v.z, n2);  d2 = fmaf(e, m.z, d2);
            n3 = fmaf(e, v.w, n3);  d3 = fmaf(e, m.w, d3);
        }
        float4 o;
        o.x = n0 / d0; o.y = n1 / d1; o.z = n2 / d2; o.w = n3 / d3;
        *(float4*)&g_x[(b*SQ + q0 + q)*(Hh*DIM) + h*DIM + dq*4] = o;
    }
}

// ---------------------------------------------------------------------------
// K3: y = x @ wo + bo  (x: [1024,256], wo: [256,128]); 8 rows/block.
// ---------------------------------------------------------------------------
__global__ void __launch_bounds__(128) out_kernel(
    const float* __restrict__ wo, const float* __restrict__ bo,
    float* __restrict__ out)
{
    __shared__ float xt[256*8];       // transposed [p][r], 8 KB
    int row0 = blockIdx.x * 8;
    int t = threadIdx.x;

    #pragma unroll
    for (int r = 0; r < 8; r++) {
        xt[t*8 + r]       = g_x[(row0+r)*256 + t];
        xt[(t+128)*8 + r] = g_x[(row0+r)*256 + t + 128];
    }
    __syncthreads();

    float acc[8];
    float bb = bo[t];
    #pragma unroll
    for (int r = 0; r < 8; r++) acc[r] = bb;

    const float4* x4 = (const float4*)xt;
    #pragma unroll 4
    for (int p = 0; p < 256; p++) {
        float w = wo[p*NH + t];
        float4 a = x4[p*2], c = x4[p*2+1];
        acc[0] = fmaf(a.x, w, acc[0]);
        acc[1] = fmaf(a.y, w, acc[1]);
        acc[2] = fmaf(a.z, w, acc[2]);
        acc[3] = fmaf(a.w, w, acc[3]);
        acc[4] = fmaf(c.x, w, acc[4]);
        acc[5] = fmaf(c.y, w, acc[5]);
        acc[6] = fmaf(c.z, w, acc[6]);
        acc[7] = fmaf(c.w, w, acc[7]);
    }
    #pragma unroll
    for (int r = 0; r < 8; r++) out[(row0+r)*NH + t] = acc[r];
}

// ---------------------------------------------------------------------------
extern "C" void kernel_launch(void* const* d_in, const int* in_sizes, int n_in,
                              void* d_out, int out_size)
{
    // Disambiguate input ordering: dict order has emb_mask (32768 elems) at
    // index 4; function-parameter order has w1 (4096 elems) there.
    bool dictOrder = (in_sizes[4] == Bn*SK*DIM);

    const float *qv, *kv, *val, *imp, *w1, *b1, *w2, *wq, *bq, *wk, *bk,
                *wo, *bo, *wd1, *bd1, *lng, *lnb, *wd2, *bd2;
    const int* mask;

    if (dictOrder) {
        qv  = (const float*)d_in[0];  kv  = (const float*)d_in[1];
        val = (const float*)d_in[2];  imp = (const float*)d_in[3];
        mask= (const int*)  d_in[4];
        w1  = (const float*)d_in[5];  b1  = (const float*)d_in[6];
        w2  = (const float*)d_in[7];
        wq  = (const float*)d_in[8];  bq  = (const float*)d_in[9];
        wk  = (const float*)d_in[10]; bk  = (const float*)d_in[11];
        wo  = (const float*)d_in[12]; bo  = (const float*)d_in[13];
        wd1 = (const float*)d_in[14]; bd1 = (const float*)d_in[15];
        lng = (const float*)d_in[16]; lnb = (const float*)d_in[17];
        wd2 = (const float*)d_in[18]; bd2 = (const float*)d_in[19];
    } else {
        qv  = (const float*)d_in[0];  kv  = (const float*)d_in[1];
        val = (const float*)d_in[2];  imp = (const float*)d_in[3];
        w1  = (const float*)d_in[4];  b1  = (const float*)d_in[5];
        w2  = (const float*)d_in[6];
        wq  = (const float*)d_in[7];  bq  = (const float*)d_in[8];
        wk  = (const float*)d_in[9];  bk  = (const float*)d_in[10];
        wo  = (const float*)d_in[11]; bo  = (const float*)d_in[12];
        wd1 = (const float*)d_in[13]; bd1 = (const float*)d_in[14];
        lng = (const float*)d_in[15]; lnb = (const float*)d_in[16];
        wd2 = (const float*)d_in[17]; bd2 = (const float*)d_in[18];
        mask= (const int*)  d_in[19];
    }

    float* y  = (float*)d_out;                       // [8,128,128]
    float* qd = (float*)d_out + Bn*SQ*NH;            // [8,128,128]

    fused1_kernel<<<640, 128>>>(qv, kv, w1, b1, w2, wq, bq, wk, bk,
                                imp, wd1, bd1, lng, lnb, wd2, bd2, qd);
    attn_kernel<<<Bn*Hh*8, 128>>>(val, mask);
    out_kernel<<<Bn*SQ/8, 128>>>(wo, bo, y);
}

// round 3
// speedup vs baseline: 1.2582x; 1.1270x over previous
#include <cuda_runtime.h>
#include <math.h>
#include <stdint.h>

#define Bn  8
#define SQ  128
#define SK  128
#define IVD 32
#define DIM 32
#define EV  64
#define Hh  8
#define NH  128
#define DKd 8

// scratch (allocation-free rule: device globals)
__device__ float g_q[Bn*SQ*EV];
__device__ float g_k[Bn*SK*EV];
__device__ float g_x[Bn*SQ*Hh*DIM];

__device__ __forceinline__ void cp_async16(uint32_t saddr, const void* gaddr) {
    asm volatile("cp.async.cg.shared.global [%0], [%1], 16;\n"
                 :: "r"(saddr), "l"(gaddr));
}
__device__ __forceinline__ void cp_commit() {
    asm volatile("cp.async.commit_group;\n");
}
__device__ __forceinline__ void cp_wait0() {
    asm volatile("cp.async.wait_group 0;\n");
}

// ---------------------------------------------------------------------------
// Fused kernel 1:
//   blocks [0,256):   proj — 8 rows/block of the 2048-row combined q/k set:
//                     e = tanh(X@w1+b1)@w2 ; q/k = e@{wq,wk}+{bq,bk}
//                     w2 staged to smem via cp.async, overlapped with phase 1.
//   blocks [256,384): impute MLP — 8 rows/block:
//                     qd = relu(LN(imp@wd1+bd1)) @ wd2 + bd2
// ---------------------------------------------------------------------------
__global__ void __launch_bounds__(128) fused1_kernel(
    const float* __restrict__ qv, const float* __restrict__ kv,
    const float* __restrict__ w1, const float* __restrict__ b1,
    const float* __restrict__ w2,
    const float* __restrict__ wq, const float* __restrict__ bq,
    const float* __restrict__ wk, const float* __restrict__ bk,
    const float* __restrict__ imp,
    const float* __restrict__ wd1, const float* __restrict__ bd1,
    const float* __restrict__ lng, const float* __restrict__ lnb,
    const float* __restrict__ wd2, const float* __restrict__ bd2,
    float* __restrict__ qd_out)
{
    __shared__ __align__(16) float smem[10240];   // 40 KB, reused per branch
    int t = threadIdx.x;

    if (blockIdx.x < 256) {
        // ---------------- proj part (8 rows/block) ----------------
        float* xs  = smem;           // [8][32]        256 f
        float* ht  = smem + 256;     // [128][8] (tr)  1024 f
        float* et  = smem + 1280;    // [64][8]  (tr)  512 f
        float* ws2 = smem + 1792;    // [128][64]      8192 f

        int r0 = blockIdx.x * 8;               // global row in [0,2048)
        bool isQ = r0 < Bn*SQ;
        int rr0 = isQ ? r0 : r0 - Bn*SQ;
        const float* xin = isQ ? qv : kv;
        const float* wp  = isQ ? wq : wk;
        const float* bp  = isQ ? bq : bk;
        float* outp      = isQ ? g_q : g_k;

        // stage w2 into smem (fire-and-forget; latency hidden by phase 1)
        {
            uint32_t sb = (uint32_t)__cvta_generic_to_shared(ws2);
            #pragma unroll
            for (int j = 0; j < 16; j++) {
                int idx = t + j*128;                  // float4 index, 2048 total
                cp_async16(sb + idx*16, w2 + idx*4);
            }
            cp_commit();
        }

        xs[t]       = xin[rr0*IVD + t];
        xs[t + 128] = xin[rr0*IVD + t + 128];
        __syncthreads();

        // phase 1: hidden col t for 8 rows
        {
            float bb = b1[t];
            float a[8];
            #pragma unroll
            for (int r = 0; r < 8; r++) a[r] = bb;
            #pragma unroll
            for (int i = 0; i < IVD; i++) {
                float w = w1[i*NH + t];
                #pragma unroll
                for (int r = 0; r < 8; r++) a[r] = fmaf(xs[r*IVD + i], w, a[r]);
            }
            float4 h0, h1;
            h0.x = tanhf(a[0]); h0.y = tanhf(a[1]);
            h0.z = tanhf(a[2]); h0.w = tanhf(a[3]);
            h1.x = tanhf(a[4]); h1.y = tanhf(a[5]);
            h1.z = tanhf(a[6]); h1.w = tanhf(a[7]);
            ((float4*)ht)[t*2]     = h0;
            ((float4*)ht)[t*2 + 1] = h1;
        }
        cp_wait0();
        __syncthreads();

        int c  = t & 63;
        int rh = (t >> 6) * 4;        // rows rh..rh+3

        // phase 2: embed (all-smem)
        {
            float a0=0.f, a1=0.f, a2=0.f, a3=0.f;
            #pragma unroll 8
            for (int p = 0; p < NH; p++) {
                float w = ws2[p*EV + c];
                float4 h = *(const float4*)&ht[p*8 + rh];
                a0 = fmaf(h.x, w, a0);
                a1 = fmaf(h.y, w, a1);
                a2 = fmaf(h.z, w, a2);
                a3 = fmaf(h.w, w, a3);
            }
            float4 o; o.x=a0; o.y=a1; o.z=a2; o.w=a3;
            *(float4*)&et[c*8 + rh] = o;
        }
        __syncthreads();

        // phase 3: q/k projection
        {
            float bb = bp[c];
            float a0=bb, a1=bb, a2=bb, a3=bb;
            #pragma unroll 8
            for (int p = 0; p < EV; p++) {
                float w = wp[p*EV + c];
                float4 e = *(const float4*)&et[p*8 + rh];
                a0 = fmaf(e.x, w, a0);
                a1 = fmaf(e.y, w, a1);
                a2 = fmaf(e.z, w, a2);
                a3 = fmaf(e.w, w, a3);
            }
            outp[(rr0+rh+0)*EV + c] = a0;
            outp[(rr0+rh+1)*EV + c] = a1;
            outp[(rr0+rh+2)*EV + c] = a2;
            outp[(rr0+rh+3)*EV + c] = a3;
        }
    } else {
        // ---------------- impute MLP part (8 rows/block) ----------------
        float* xi   = smem;            // 128 f
        float* htm  = smem + 128;      // [128][8] transposed, 1024 f
        float* redS = smem + 1152;     // 32 f
        float* redQ = smem + 1184;     // 32 f

        int row0 = (blockIdx.x - 256) * 8;
        xi[t] = imp[row0*16 + t];
        __syncthreads();

        float a[8];
        {
            float bb = bd1[t];
            #pragma unroll
            for (int r = 0; r < 8; r++) a[r] = bb;
            #pragma unroll
            for (int i = 0; i < 16; i++) {
                float w = wd1[i*NH + t];
                #pragma unroll
                for (int r = 0; r < 8; r++) a[r] = fmaf(xi[r*16+i], w, a[r]);
            }
        }

        float ss[8], qq[8];
        #pragma unroll
        for (int r = 0; r < 8; r++) { ss[r] = a[r]; qq[r] = a[r]*a[r]; }
        #pragma unroll
        for (int off = 16; off > 0; off >>= 1) {
            #pragma unroll
            for (int r = 0; r < 8; r++) {
                ss[r] += __shfl_xor_sync(0xffffffff, ss[r], off);
                qq[r] += __shfl_xor_sync(0xffffffff, qq[r], off);
            }
        }
        int wid = t >> 5, lane = t & 31;
        if (lane == 0) {
            #pragma unroll
            for (int r = 0; r < 8; r++) { redS[wid*8+r] = ss[r]; redQ[wid*8+r] = qq[r]; }
        }
        __syncthreads();

        float g = lng[t], be = lnb[t];
        #pragma unroll
        for (int r = 0; r < 8; r++) {
            float S = redS[r] + redS[8+r] + redS[16+r] + redS[24+r];
            float Q = redQ[r] + redQ[8+r] + redQ[16+r] + redQ[24+r];
            float mu  = S * (1.f/128.f);
            float var = Q * (1.f/128.f) - mu*mu;
            float ln = (a[r] - mu) * rsqrtf(var + 1e-5f) * g + be;
            htm[t*8 + r] = fmaxf(ln, 0.f);
        }
        __syncthreads();

        float acc[8];
        {
            float bb = bd2[t];
            #pragma unroll
            for (int r = 0; r < 8; r++) acc[r] = bb;
            const float4* h4 = (const float4*)htm;
            #pragma unroll 8
            for (int p = 0; p < NH; p++) {
                float w = wd2[p*NH + t];
                float4 x0 = h4[p*2], x1 = h4[p*2+1];
                acc[0] = fmaf(x0.x, w, acc[0]);
                acc[1] = fmaf(x0.y, w, acc[1]);
                acc[2] = fmaf(x0.z, w, acc[2]);
                acc[3] = fmaf(x0.w, w, acc[3]);
                acc[4] = fmaf(x1.x, w, acc[4]);
                acc[5] = fmaf(x1.y, w, acc[5]);
                acc[6] = fmaf(x1.z, w, acc[6]);
                acc[7] = fmaf(x1.w, w, acc[7]);
            }
        }
        #pragma unroll
        for (int r = 0; r < 8; r++) qd_out[(row0+r)*NH + t] = acc[r];
    }
}

// ---------------------------------------------------------------------------
// K2: masked-softmax attention.
// out[b,h,q,d] = sum_k m[b,k,d]*e_k*v[b,k,d] / sum_k m[b,k,d]*e_k
// e_k = exp((s_k - max)/sqrt(DK)); masked logits underflow to exactly 0.
// grid = B*H*8 (16-q tiles), 128 threads.
// ---------------------------------------------------------------------------
__global__ void __launch_bounds__(128) attn_kernel(
    const float* __restrict__ value, const int* __restrict__ mask)
{
    __shared__ float qs[16*DKd];      // 0.5 KB
    __shared__ float ks[SK*DKd];      // 4 KB
    __shared__ float mv[SK*DIM];      // 16 KB  mask*value
    __shared__ float mf[SK*DIM];      // 16 KB  mask as float
    __shared__ float es[16*SK];       // 8 KB   exp weights

    int blk = blockIdx.x;             // b*64 + h*8 + qg
    int qg  = blk & 7;
    int h   = (blk >> 3) & 7;
    int b   = blk >> 6;
    int q0  = qg * 16;
    int t   = threadIdx.x;

    qs[t] = g_q[(b*SQ + q0 + (t>>3))*EV + h*DKd + (t&7)];
    #pragma unroll
    for (int j = 0; j < 8; j++) {
        int idx = t + j*128;          // over 1024 = 128k x 8d
        ks[idx] = g_k[(b*SK + (idx>>3))*EV + h*DKd + (idx&7)];
    }
    {
        const float4* v4 = (const float4*)(value + b*SK*DIM);
        const int4*   m4 = (const int4*)  (mask  + b*SK*DIM);
        float4* mv4 = (float4*)mv;
        float4* mf4 = (float4*)mf;
        #pragma unroll
        for (int j = 0; j < 8; j++) {
            int idx = t + j*128;      // over 1024 float4s
            int4 mm = m4[idx]; float4 vv = v4[idx];
            float4 av, af;
            av.x = mm.x ? vv.x : 0.f;  af.x = mm.x ? 1.f : 0.f;
            av.y = mm.y ? vv.y : 0.f;  af.y = mm.y ? 1.f : 0.f;
            av.z = mm.z ? vv.z : 0.f;  af.z = mm.z ? 1.f : 0.f;
            av.w = mm.w ? vv.w : 0.f;  af.w = mm.w ? 1.f : 0.f;
            mv4[idx] = av; mf4[idx] = af;
        }
    }
    __syncthreads();

    const float scale = 0.35355339059327373f;   // 1/sqrt(8)

    // ---------------- phase A: scores + softmax weights ----------------
    {
        int q  = t >> 3;              // 0..15
        int kq = t & 7;               // k range [kq*16, kq*16+16)
        float qr[DKd];
        #pragma unroll
        for (int j = 0; j < DKd; j++) qr[j] = qs[q*DKd + j];

        float s[16];
        int kbase = kq * 16;
        #pragma unroll
        for (int i = 0; i < 16; i++) {
            const float4* kp = (const float4*)&ks[(kbase+i)*DKd];
            float4 k0 = kp[0], k1 = kp[1];
            float acc = qr[0]*k0.x;
            acc = fmaf(qr[1], k0.y, acc);
            acc = fmaf(qr[2], k0.z, acc);
            acc = fmaf(qr[3], k0.w, acc);
            acc = fmaf(qr[4], k1.x, acc);
            acc = fmaf(qr[5], k1.y, acc);
            acc = fmaf(qr[6], k1.z, acc);
            acc = fmaf(qr[7], k1.w, acc);
            s[i] = acc;
        }
        float mx = s[0];
        #pragma unroll
        for (int i = 1; i < 16; i++) mx = fmaxf(mx, s[i]);
        mx = fmaxf(mx, __shfl_xor_sync(0xffffffff, mx, 1));
        mx = fmaxf(mx, __shfl_xor_sync(0xffffffff, mx, 2));
        mx = fmaxf(mx, __shfl_xor_sync(0xffffffff, mx, 4));
        float msc = mx * scale;
        #pragma unroll
        for (int i = 0; i < 16; i++)
            es[q*SK + kbase + i] = __expf(fmaf(s[i], scale, -msc));
    }
    __syncthreads();

    // ---------------- phase B: masked weighted accumulation ----------------
    {
        int q  = t >> 3;              // 0..15
        int dq = t & 7;               // d range [dq*4, dq*4+4)
        float n0=0.f, n1=0.f, n2=0.f, n3=0.f;
        float d0=0.f, d1=0.f, d2=0.f, d3=0.f;
        const float4* mv4 = (const float4*)mv;
        const float4* mf4 = (const float4*)mf;
        const float4* ep4 = (const float4*)&es[q*SK];
        #pragma unroll 4
        for (int k4 = 0; k4 < SK/4; k4++) {
            float4 e4 = ep4[k4];
            #pragma unroll
            for (int j = 0; j < 4; j++) {
                float e = (j==0) ? e4.x : (j==1) ? e4.y : (j==2) ? e4.z : e4.w;
                int k = k4*4 + j;
                float4 v = mv4[k*8 + dq];
                float4 m = mf4[k*8 + dq];
                n0 = fmaf(e, v.x, n0);  d0 = fmaf(e, m.x, d0);
                n1 = fmaf(e, v.y, n1);  d1 = fmaf(e, m.y, d1);
                n2 = fmaf(e, v.z, n2);  d2 = fmaf(e, m.z, d2);
                n3 = fmaf(e, v.w, n3);  d3 = fmaf(e, m.w, d3);
            }
        }
        float4 o;
        o.x = n0 / d0; o.y = n1 / d1; o.z = n2 / d2; o.w = n3 / d3;
        *(float4*)&g_x[(b*SQ + q0 + q)*(Hh*DIM) + h*DIM + dq*4] = o;
    }
}

// ---------------------------------------------------------------------------
// K3: y = x @ wo + bo  (x: [1024,256], wo: [256,128]); 8 rows/block.
// ---------------------------------------------------------------------------
__global__ void __launch_bounds__(128) out_kernel(
    const float* __restrict__ wo, const float* __restrict__ bo,
    float* __restrict__ out)
{
    __shared__ float xt[256*8];       // transposed [p][r], 8 KB
    int row0 = blockIdx.x * 8;
    int t = threadIdx.x;

    #pragma unroll
    for (int r = 0; r < 8; r++) {
        xt[t*8 + r]       = g_x[(row0+r)*256 + t];
        xt[(t+128)*8 + r] = g_x[(row0+r)*256 + t + 128];
    }
    __syncthreads();

    float acc[8];
    float bb = bo[t];
    #pragma unroll
    for (int r = 0; r < 8; r++) acc[r] = bb;

    const float4* x4 = (const float4*)xt;
    #pragma unroll 8
    for (int p = 0; p < 256; p++) {
        float w = wo[p*NH + t];
        float4 a = x4[p*2], c = x4[p*2+1];
        acc[0] = fmaf(a.x, w, acc[0]);
        acc[1] = fmaf(a.y, w, acc[1]);
        acc[2] = fmaf(a.z, w, acc[2]);
        acc[3] = fmaf(a.w, w, acc[3]);
        acc[4] = fmaf(c.x, w, acc[4]);
        acc[5] = fmaf(c.y, w, acc[5]);
        acc[6] = fmaf(c.z, w, acc[6]);
        acc[7] = fmaf(c.w, w, acc[7]);
    }
    #pragma unroll
    for (int r = 0; r < 8; r++) out[(row0+r)*NH + t] = acc[r];
}

// ---------------------------------------------------------------------------
extern "C" void kernel_launch(void* const* d_in, const int* in_sizes, int n_in,
                              void* d_out, int out_size)
{
    bool dictOrder = (in_sizes[4] == Bn*SK*DIM);

    const float *qv, *kv, *val, *imp, *w1, *b1, *w2, *wq, *bq, *wk, *bk,
                *wo, *bo, *wd1, *bd1, *lng, *lnb, *wd2, *bd2;
    const int* mask;

    if (dictOrder) {
        qv  = (const float*)d_in[0];  kv  = (const float*)d_in[1];
        val = (const float*)d_in[2];  imp = (const float*)d_in[3];
        mask= (const int*)  d_in[4];
        w1  = (const float*)d_in[5];  b1  = (const float*)d_in[6];
        w2  = (const float*)d_in[7];
        wq  = (const float*)d_in[8];  bq  = (const float*)d_in[9];
        wk  = (const float*)d_in[10]; bk  = (const float*)d_in[11];
        wo  = (const float*)d_in[12]; bo  = (const float*)d_in[13];
        wd1 = (const float*)d_in[14]; bd1 = (const float*)d_in[15];
        lng = (const float*)d_in[16]; lnb = (const float*)d_in[17];
        wd2 = (const float*)d_in[18]; bd2 = (const float*)d_in[19];
    } else {
        qv  = (const float*)d_in[0];  kv  = (const float*)d_in[1];
        val = (const float*)d_in[2];  imp = (const float*)d_in[3];
        w1  = (const float*)d_in[4];  b1  = (const float*)d_in[5];
        w2  = (const float*)d_in[6];
        wq  = (const float*)d_in[7];  bq  = (const float*)d_in[8];
        wk  = (const float*)d_in[9];  bk  = (const float*)d_in[10];
        wo  = (const float*)d_in[11]; bo  = (const float*)d_in[12];
        wd1 = (const float*)d_in[13]; bd1 = (const float*)d_in[14];
        lng = (const float*)d_in[15]; lnb = (const float*)d_in[16];
        wd2 = (const float*)d_in[17]; bd2 = (const float*)d_in[18];
        mask= (const int*)  d_in[19];
    }

    float* y  = (float*)d_out;                       // [8,128,128]
    float* qd = (float*)d_out + Bn*SQ*NH;            // [8,128,128]

    fused1_kernel<<<384, 128>>>(qv, kv, w1, b1, w2, wq, bq, wk, bk,
                                imp, wd1, bd1, lng, lnb, wd2, bd2, qd);
    attn_kernel<<<Bn*Hh*8, 128>>>(val, mask);
    out_kernel<<<Bn*SQ/8, 128>>>(wo, bo, y);
}

// round 4
// speedup vs baseline: 1.4540x; 1.1556x over previous
#include <cuda_runtime.h>
#include <math.h>
#include <stdint.h>

#define Bn  8
#define SQ  128
#define SK  128
#define IVD 32
#define DIM 32
#define EV  64
#define Hh  8
#define NH  128
#define DKd 8

// scratch (allocation-free rule: device globals)
__device__ float g_q[Bn*SQ*EV];
__device__ float g_k[Bn*SK*EV];
__device__ float g_x[Bn*SQ*Hh*DIM];

__device__ __forceinline__ void cp_async16(uint32_t saddr, const void* gaddr) {
    asm volatile("cp.async.cg.shared.global [%0], [%1], 16;\n"
                 :: "r"(saddr), "l"(gaddr));
}
__device__ __forceinline__ void cp_commit() {
    asm volatile("cp.async.commit_group;\n");
}
__device__ __forceinline__ void cp_wait0() {
    asm volatile("cp.async.wait_group 0;\n");
}

__device__ __forceinline__ float fast_tanh(float x) {
    x = fminf(fmaxf(x, -15.f), 15.f);
    float e = __expf(2.f * x);
    return __fdividef(e - 1.f, e + 1.f);
}

// ---------------------------------------------------------------------------
// Fused kernel 1 (256 threads):
//   blocks [0,256):   proj — 8 rows/block of the 2048-row combined q/k set
//   blocks [256,384): impute MLP — 8 rows/block
// ---------------------------------------------------------------------------
__global__ void __launch_bounds__(256) fused1_kernel(
    const float* __restrict__ qv, const float* __restrict__ kv,
    const float* __restrict__ w1, const float* __restrict__ b1,
    const float* __restrict__ w2,
    const float* __restrict__ wq, const float* __restrict__ bq,
    const float* __restrict__ wk, const float* __restrict__ bk,
    const float* __restrict__ imp,
    const float* __restrict__ wd1, const float* __restrict__ bd1,
    const float* __restrict__ lng, const float* __restrict__ lnb,
    const float* __restrict__ wd2, const float* __restrict__ bd2,
    float* __restrict__ qd_out)
{
    __shared__ __align__(16) float smem[10240];   // 40 KB, reused per branch
    int t = threadIdx.x;

    if (blockIdx.x < 256) {
        // ---------------- proj (8 rows/block) ----------------
        float* xs  = smem;           // [8][32]        256 f
        float* ht  = smem + 256;     // [128][8] (tr)  1024 f
        float* et  = smem + 1280;    // [64][8]  (tr)  512 f
        float* ws2 = smem + 1792;    // [128][64]      8192 f

        int r0 = blockIdx.x * 8;               // global row in [0,2048)
        bool isQ = r0 < Bn*SQ;
        int rr0 = isQ ? r0 : r0 - Bn*SQ;
        const float* xin = isQ ? qv : kv;
        const float* wp  = isQ ? wq : wk;
        const float* bp  = isQ ? bq : bk;
        float* outp      = isQ ? g_q : g_k;

        // stage w2 (fire-and-forget; latency hidden by phase 1)
        {
            uint32_t sb = (uint32_t)__cvta_generic_to_shared(ws2);
            #pragma unroll
            for (int j = 0; j < 8; j++) {
                int idx = t + j*256;           // float4 index, 2048 total
                cp_async16(sb + idx*16, w2 + idx*4);
            }
            cp_commit();
        }

        xs[t] = xin[rr0*IVD + t];              // 256 f = 8 rows x 32
        __syncthreads();

        // phase 1: hidden. thread = (col c1, 4 rows rh1..rh1+3)
        {
            int c1  = t & 127;
            int rh1 = (t >> 7) * 4;
            float bb = b1[c1];
            float a0=bb, a1=bb, a2=bb, a3=bb;
            #pragma unroll
            for (int i = 0; i < IVD; i++) {
                float w = w1[i*NH + c1];
                a0 = fmaf(xs[(rh1+0)*IVD + i], w, a0);
                a1 = fmaf(xs[(rh1+1)*IVD + i], w, a1);
                a2 = fmaf(xs[(rh1+2)*IVD + i], w, a2);
                a3 = fmaf(xs[(rh1+3)*IVD + i], w, a3);
            }
            float4 h;
            h.x = fast_tanh(a0); h.y = fast_tanh(a1);
            h.z = fast_tanh(a2); h.w = fast_tanh(a3);
            *(float4*)&ht[c1*8 + rh1] = h;
        }
        cp_wait0();
        __syncthreads();

        int c  = t & 63;
        int rh = (t >> 6) * 2;        // rows rh, rh+1

        // phase 2: embed (all-smem)
        {
            float a0 = 0.f, a1 = 0.f;
            #pragma unroll 8
            for (int p = 0; p < NH; p++) {
                float w = ws2[p*EV + c];
                float2 h = *(const float2*)&ht[p*8 + rh];
                a0 = fmaf(h.x, w, a0);
                a1 = fmaf(h.y, w, a1);
            }
            float2 o; o.x = a0; o.y = a1;
            *(float2*)&et[c*8 + rh] = o;
        }
        __syncthreads();

        // phase 3: q/k projection
        {
            float bb = bp[c];
            float a0 = bb, a1 = bb;
            #pragma unroll 8
            for (int p = 0; p < EV; p++) {
                float w = wp[p*EV + c];
                float2 e = *(const float2*)&et[p*8 + rh];
                a0 = fmaf(e.x, w, a0);
                a1 = fmaf(e.y, w, a1);
            }
            outp[(rr0+rh+0)*EV + c] = a0;
            outp[(rr0+rh+1)*EV + c] = a1;
        }
    } else {
        // ---------------- impute MLP (8 rows/block, 256 thr) ----------------
        float* xi   = smem;            // [8][16] 128 f
        float* htm  = smem + 128;      // [128][8] transposed, 1024 f
        float* redS = smem + 1152;     // 32 f  (warp x 4 rows)
        float* redQ = smem + 1184;     // 32 f

        int row0 = (blockIdx.x - 256) * 8;
        if (t < 128) xi[t] = imp[row0*16 + t];
        __syncthreads();

        int c1   = t & 127;
        int base = (t >> 7) * 4;       // rows base..base+3
        int w8   = t >> 5;             // warp 0..7
        int lane = t & 31;

        float a[4];
        {
            float bb = bd1[c1];
            #pragma unroll
            for (int j = 0; j < 4; j++) a[j] = bb;
            #pragma unroll
            for (int i = 0; i < 16; i++) {
                float w = wd1[i*NH + c1];
                #pragma unroll
                for (int j = 0; j < 4; j++)
                    a[j] = fmaf(xi[(base+j)*16 + i], w, a[j]);
            }
        }

        float ss[4], qq[4];
        #pragma unroll
        for (int j = 0; j < 4; j++) { ss[j] = a[j]; qq[j] = a[j]*a[j]; }
        #pragma unroll
        for (int off = 16; off > 0; off >>= 1) {
            #pragma unroll
            for (int j = 0; j < 4; j++) {
                ss[j] += __shfl_xor_sync(0xffffffff, ss[j], off);
                qq[j] += __shfl_xor_sync(0xffffffff, qq[j], off);
            }
        }
        if (lane == 0) {
            #pragma unroll
            for (int j = 0; j < 4; j++) { redS[w8*4+j] = ss[j]; redQ[w8*4+j] = qq[j]; }
        }
        __syncthreads();

        float g = lng[c1], be = lnb[c1];
        int gw = (base == 0) ? 0 : 4;      // contributing warp group
        {
            float4 hv;
            float* hp = (float*)&hv;
            #pragma unroll
            for (int j = 0; j < 4; j++) {
                float S = redS[(gw+0)*4+j] + redS[(gw+1)*4+j]
                        + redS[(gw+2)*4+j] + redS[(gw+3)*4+j];
                float Q = redQ[(gw+0)*4+j] + redQ[(gw+1)*4+j]
                        + redQ[(gw+2)*4+j] + redQ[(gw+3)*4+j];
                float mu  = S * (1.f/128.f);
                float var = Q * (1.f/128.f) - mu*mu;
                float ln = (a[j] - mu) * rsqrtf(var + 1e-5f) * g + be;
                hp[j] = fmaxf(ln, 0.f);
            }
            *(float4*)&htm[c1*8 + base] = hv;
        }
        __syncthreads();

        float acc[4];
        {
            float bb = bd2[c1];
            #pragma unroll
            for (int j = 0; j < 4; j++) acc[j] = bb;
            #pragma unroll 8
            for (int p = 0; p < NH; p++) {
                float w = wd2[p*NH + c1];
                float4 h = *(const float4*)&htm[p*8 + base];
                acc[0] = fmaf(h.x, w, acc[0]);
                acc[1] = fmaf(h.y, w, acc[1]);
                acc[2] = fmaf(h.z, w, acc[2]);
                acc[3] = fmaf(h.w, w, acc[3]);
            }
        }
        #pragma unroll
        for (int j = 0; j < 4; j++)
            qd_out[(row0+base+j)*NH + c1] = acc[j];
    }
}

// ---------------------------------------------------------------------------
// K2: masked-softmax attention (unchanged structure).
// grid = B*H*8 (16-q tiles), 128 threads.
// ---------------------------------------------------------------------------
__global__ void __launch_bounds__(128) attn_kernel(
    const float* __restrict__ value, const int* __restrict__ mask)
{
    __shared__ float qs[16*DKd];
    __shared__ float ks[SK*DKd];
    __shared__ float mv[SK*DIM];
    __shared__ float mf[SK*DIM];
    __shared__ float es[16*SK];

    int blk = blockIdx.x;
    int qg  = blk & 7;
    int h   = (blk >> 3) & 7;
    int b   = blk >> 6;
    int q0  = qg * 16;
    int t   = threadIdx.x;

    qs[t] = g_q[(b*SQ + q0 + (t>>3))*EV + h*DKd + (t&7)];
    #pragma unroll
    for (int j = 0; j < 8; j++) {
        int idx = t + j*128;
        ks[idx] = g_k[(b*SK + (idx>>3))*EV + h*DKd + (idx&7)];
    }
    {
        const float4* v4 = (const float4*)(value + b*SK*DIM);
        const int4*   m4 = (const int4*)  (mask  + b*SK*DIM);
        float4* mv4 = (float4*)mv;
        float4* mf4 = (float4*)mf;
        #pragma unroll
        for (int j = 0; j < 8; j++) {
            int idx = t + j*128;
            int4 mm = m4[idx]; float4 vv = v4[idx];
            float4 av, af;
            av.x = mm.x ? vv.x : 0.f;  af.x = mm.x ? 1.f : 0.f;
            av.y = mm.y ? vv.y : 0.f;  af.y = mm.y ? 1.f : 0.f;
            av.z = mm.z ? vv.z : 0.f;  af.z = mm.z ? 1.f : 0.f;
            av.w = mm.w ? vv.w : 0.f;  af.w = mm.w ? 1.f : 0.f;
            mv4[idx] = av; mf4[idx] = af;
        }
    }
    __syncthreads();

    const float scale = 0.35355339059327373f;   // 1/sqrt(8)

    // phase A: scores + softmax weights
    {
        int q  = t >> 3;
        int kq = t & 7;
        float qr[DKd];
        #pragma unroll
        for (int j = 0; j < DKd; j++) qr[j] = qs[q*DKd + j];

        float s[16];
        int kbase = kq * 16;
        #pragma unroll
        for (int i = 0; i < 16; i++) {
            const float4* kp = (const float4*)&ks[(kbase+i)*DKd];
            float4 k0 = kp[0], k1 = kp[1];
            float acc = qr[0]*k0.x;
            acc = fmaf(qr[1], k0.y, acc);
            acc = fmaf(qr[2], k0.z, acc);
            acc = fmaf(qr[3], k0.w, acc);
            acc = fmaf(qr[4], k1.x, acc);
            acc = fmaf(qr[5], k1.y, acc);
            acc = fmaf(qr[6], k1.z, acc);
            acc = fmaf(qr[7], k1.w, acc);
            s[i] = acc;
        }
        float mx = s[0];
        #pragma unroll
        for (int i = 1; i < 16; i++) mx = fmaxf(mx, s[i]);
        mx = fmaxf(mx, __shfl_xor_sync(0xffffffff, mx, 1));
        mx = fmaxf(mx, __shfl_xor_sync(0xffffffff, mx, 2));
        mx = fmaxf(mx, __shfl_xor_sync(0xffffffff, mx, 4));
        float msc = mx * scale;
        #pragma unroll
        for (int i = 0; i < 16; i++)
            es[q*SK + kbase + i] = __expf(fmaf(s[i], scale, -msc));
    }
    __syncthreads();

    // phase B: masked weighted accumulation
    {
        int q  = t >> 3;
        int dq = t & 7;
        float n0=0.f, n1=0.f, n2=0.f, n3=0.f;
        float d0=0.f, d1=0.f, d2=0.f, d3=0.f;
        const float4* mv4 = (const float4*)mv;
        const float4* mf4 = (const float4*)mf;
        const float4* ep4 = (const float4*)&es[q*SK];
        #pragma unroll 4
        for (int k4 = 0; k4 < SK/4; k4++) {
            float4 e4 = ep4[k4];
            #pragma unroll
            for (int j = 0; j < 4; j++) {
                float e = (j==0) ? e4.x : (j==1) ? e4.y : (j==2) ? e4.z : e4.w;
                int k = k4*4 + j;
                float4 v = mv4[k*8 + dq];
                float4 m = mf4[k*8 + dq];
                n0 = fmaf(e, v.x, n0);  d0 = fmaf(e, m.x, d0);
                n1 = fmaf(e, v.y, n1);  d1 = fmaf(e, m.y, d1);
                n2 = fmaf(e, v.z, n2);  d2 = fmaf(e, m.z, d2);
                n3 = fmaf(e, v.w, n3);  d3 = fmaf(e, m.w, d3);
            }
        }
        float4 o;
        o.x = __fdividef(n0, d0); o.y = __fdividef(n1, d1);
        o.z = __fdividef(n2, d2); o.w = __fdividef(n3, d3);
        *(float4*)&g_x[(b*SQ + q0 + q)*(Hh*DIM) + h*DIM + dq*4] = o;
    }
}

// ---------------------------------------------------------------------------
// K3: y = x @ wo + bo. 8 rows/block, 512 threads: 4-way split over p.
// ---------------------------------------------------------------------------
__global__ void __launch_bounds__(512) out_kernel(
    const float* __restrict__ wo, const float* __restrict__ bo,
    float* __restrict__ out)
{
    __shared__ float xt[256*8];       // transposed [p][r], 8 KB
    __shared__ float red[3*1024];     // partials from segs 1..3, 12 KB
    int row0 = blockIdx.x * 8;
    int t = threadIdx.x;

    // stage x tile (2048 contiguous floats), transposed into smem
    #pragma unroll
    for (int j = 0; j < 4; j++) {
        int idx = t + j*512;          // 0..2047
        int r = idx >> 8, p = idx & 255;
        xt[p*8 + r] = g_x[row0*256 + idx];
    }
    __syncthreads();

    int c   = t & 127;
    int seg = t >> 7;                 // 0..3, p range [seg*64, seg*64+64)
    int p0  = seg * 64;

    float acc[8];
    #pragma unroll
    for (int r = 0; r < 8; r++) acc[r] = 0.f;

    const float4* x4 = (const float4*)xt;
    #pragma unroll 8
    for (int pi = 0; pi < 64; pi++) {
        int p = p0 + pi;
        float w = wo[p*NH + c];
        float4 a = x4[p*2], b = x4[p*2+1];
        acc[0] = fmaf(a.x, w, acc[0]);
        acc[1] = fmaf(a.y, w, acc[1]);
        acc[2] = fmaf(a.z, w, acc[2]);
        acc[3] = fmaf(a.w, w, acc[3]);
        acc[4] = fmaf(b.x, w, acc[4]);
        acc[5] = fmaf(b.y, w, acc[5]);
        acc[6] = fmaf(b.z, w, acc[6]);
        acc[7] = fmaf(b.w, w, acc[7]);
    }

    if (seg > 0) {
        float* rp = &red[(seg-1)*1024];
        #pragma unroll
        for (int r = 0; r < 8; r++) rp[r*128 + c] = acc[r];
    }
    __syncthreads();
    if (seg == 0) {
        float bb = bo[c];
        #pragma unroll
        for (int r = 0; r < 8; r++) {
            float v = acc[r] + bb + red[r*128 + c] + red[1024 + r*128 + c]
                    + red[2048 + r*128 + c];
            out[(row0+r)*NH + c] = v;
        }
    }
}

// ---------------------------------------------------------------------------
extern "C" void kernel_launch(void* const* d_in, const int* in_sizes, int n_in,
                              void* d_out, int out_size)
{
    bool dictOrder = (in_sizes[4] == Bn*SK*DIM);

    const float *qv, *kv, *val, *imp, *w1, *b1, *w2, *wq, *bq, *wk, *bk,
                *wo, *bo, *wd1, *bd1, *lng, *lnb, *wd2, *bd2;
    const int* mask;

    if (dictOrder) {
        qv  = (const float*)d_in[0];  kv  = (const float*)d_in[1];
        val = (const float*)d_in[2];  imp = (const float*)d_in[3];
        mask= (const int*)  d_in[4];
        w1  = (const float*)d_in[5];  b1  = (const float*)d_in[6];
        w2  = (const float*)d_in[7];
        wq  = (const float*)d_in[8];  bq  = (const float*)d_in[9];
        wk  = (const float*)d_in[10]; bk  = (const float*)d_in[11];
        wo  = (const float*)d_in[12]; bo  = (const float*)d_in[13];
        wd1 = (const float*)d_in[14]; bd1 = (const float*)d_in[15];
        lng = (const float*)d_in[16]; lnb = (const float*)d_in[17];
        wd2 = (const float*)d_in[18]; bd2 = (const float*)d_in[19];
    } else {
        qv  = (const float*)d_in[0];  kv  = (const float*)d_in[1];
        val = (const float*)d_in[2];  imp = (const float*)d_in[3];
        w1  = (const float*)d_in[4];  b1  = (const float*)d_in[5];
        w2  = (const float*)d_in[6];
        wq  = (const float*)d_in[7];  bq  = (const float*)d_in[8];
        wk  = (const float*)d_in[9];  bk  = (const float*)d_in[10];
        wo  = (const float*)d_in[11]; bo  = (const float*)d_in[12];
        wd1 = (const float*)d_in[13]; bd1 = (const float*)d_in[14];
        lng = (const float*)d_in[15]; lnb = (const float*)d_in[16];
        wd2 = (const float*)d_in[17]; bd2 = (const float*)d_in[18];
        mask= (const int*)  d_in[19];
    }

    float* y  = (float*)d_out;                       // [8,128,128]
    float* qd = (float*)d_out + Bn*SQ*NH;            // [8,128,128]

    fused1_kernel<<<384, 256>>>(qv, kv, w1, b1, w2, wq, bq, wk, bk,
                                imp, wd1, bd1, lng, lnb, wd2, bd2, qd);
    attn_kernel<<<Bn*Hh*8, 128>>>(val, mask);
    out_kernel<<<Bn*SQ/8, 512>>>(wo, bo, y);
}

// round 5
// speedup vs baseline: 1.4552x; 1.0008x over previous
#include <cuda_runtime.h>
#include <math.h>
#include <stdint.h>

#define Bn  8
#define SQ  128
#define SK  128
#define IVD 32
#define DIM 32
#define EV  64
#define Hh  8
#define NH  128
#define DKd 8

// scratch (allocation-free rule: device globals)
__device__ float g_q[Bn*SQ*EV];
__device__ float g_k[Bn*SK*EV];
__device__ float g_x[Bn*SQ*Hh*DIM];

__device__ __forceinline__ void cp_async16(uint32_t saddr, const void* gaddr) {
    asm volatile("cp.async.cg.shared.global [%0], [%1], 16;\n"
                 :: "r"(saddr), "l"(gaddr));
}
__device__ __forceinline__ void cp_commit() {
    asm volatile("cp.async.commit_group;\n");
}
__device__ __forceinline__ void cp_wait0() {
    asm volatile("cp.async.wait_group 0;\n");
}

__device__ __forceinline__ float fast_tanh(float x) {
    x = fminf(fmaxf(x, -15.f), 15.f);
    float e = __expf(2.f * x);
    return __fdividef(e - 1.f, e + 1.f);
}

// ---------------------------------------------------------------------------
// K1: proj only. 128 blocks x 256 threads, 16 rows/block.
//   e = tanh(X@w1+b1)@w2 ; q/k = e@{wq,wk}+{bq,bk}
//   w2 (32KB) staged to smem via cp.async, overlapped with phase 1.
// ---------------------------------------------------------------------------
__global__ void __launch_bounds__(256) proj_kernel(
    const float* __restrict__ qv, const float* __restrict__ kv,
    const float* __restrict__ w1, const float* __restrict__ b1,
    const float* __restrict__ w2,
    const float* __restrict__ wq, const float* __restrict__ bq,
    const float* __restrict__ wk, const float* __restrict__ bk)
{
    __shared__ __align__(16) float xs_t[IVD*16];    // [i][r] transposed, 2KB
    __shared__ __align__(16) float ht[NH*16];       // [p][r] transposed, 8KB
    __shared__ __align__(16) float et[EV*16];       // [p][r] transposed, 4KB
    __shared__ __align__(16) float ws2[NH*EV];      // 32KB

    int t = threadIdx.x;
    int r0 = blockIdx.x * 16;              // global row in [0,2048)
    bool isQ = r0 < Bn*SQ;
    int rr0 = isQ ? r0 : r0 - Bn*SQ;
    const float* xin = isQ ? qv : kv;
    const float* wp  = isQ ? wq : wk;
    const float* bp  = isQ ? bq : bk;
    float* outp      = isQ ? g_q : g_k;

    // stage w2 (fire-and-forget; latency hidden by phase 1)
    {
        uint32_t sb = (uint32_t)__cvta_generic_to_shared(ws2);
        #pragma unroll
        for (int j = 0; j < 8; j++) {
            int idx = t + j*256;           // float4 index, 2048 total
            cp_async16(sb + idx*16, w2 + idx*4);
        }
        cp_commit();
    }

    // load 16 input rows, transposed [i][r]
    #pragma unroll
    for (int j = 0; j < 2; j++) {
        int idx = t + j*256;               // 0..511
        int r = idx >> 5, i = idx & 31;
        xs_t[i*16 + r] = xin[rr0*IVD + idx];
    }
    __syncthreads();

    // phase 1: hidden. thread = (col c1 of 128, 8 rows)
    {
        int c1  = t & 127;
        int rh1 = (t >> 7) * 8;
        float bb = b1[c1];
        float a[8];
        #pragma unroll
        for (int r = 0; r < 8; r++) a[r] = bb;
        #pragma unroll
        for (int i = 0; i < IVD; i++) {
            float w = w1[i*NH + c1];
            float4 x0 = *(const float4*)&xs_t[i*16 + rh1];
            float4 x1 = *(const float4*)&xs_t[i*16 + rh1 + 4];
            a[0] = fmaf(x0.x, w, a[0]);
            a[1] = fmaf(x0.y, w, a[1]);
            a[2] = fmaf(x0.z, w, a[2]);
            a[3] = fmaf(x0.w, w, a[3]);
            a[4] = fmaf(x1.x, w, a[4]);
            a[5] = fmaf(x1.y, w, a[5]);
            a[6] = fmaf(x1.z, w, a[6]);
            a[7] = fmaf(x1.w, w, a[7]);
        }
        float4 h0, h1;
        h0.x = fast_tanh(a[0]); h0.y = fast_tanh(a[1]);
        h0.z = fast_tanh(a[2]); h0.w = fast_tanh(a[3]);
        h1.x = fast_tanh(a[4]); h1.y = fast_tanh(a[5]);
        h1.z = fast_tanh(a[6]); h1.w = fast_tanh(a[7]);
        *(float4*)&ht[c1*16 + rh1]     = h0;
        *(float4*)&ht[c1*16 + rh1 + 4] = h1;
    }
    cp_wait0();
    __syncthreads();

    int c  = t & 63;
    int rg = (t >> 6) * 4;        // rows rg..rg+3

    // phase 2: embed (all-smem)
    {
        float a0=0.f, a1=0.f, a2=0.f, a3=0.f;
        #pragma unroll 8
        for (int p = 0; p < NH; p++) {
            float w = ws2[p*EV + c];
            float4 h = *(const float4*)&ht[p*16 + rg];
            a0 = fmaf(h.x, w, a0);
            a1 = fmaf(h.y, w, a1);
            a2 = fmaf(h.z, w, a2);
            a3 = fmaf(h.w, w, a3);
        }
        float4 o; o.x=a0; o.y=a1; o.z=a2; o.w=a3;
        *(float4*)&et[c*16 + rg] = o;
    }
    __syncthreads();

    // phase 3: q/k projection
    {
        float bb = bp[c];
        float a0=bb, a1=bb, a2=bb, a3=bb;
        #pragma unroll 8
        for (int p = 0; p < EV; p++) {
            float w = wp[p*EV + c];
            float4 e = *(const float4*)&et[p*16 + rg];
            a0 = fmaf(e.x, w, a0);
            a1 = fmaf(e.y, w, a1);
            a2 = fmaf(e.z, w, a2);
            a3 = fmaf(e.w, w, a3);
        }
        outp[(rr0+rg+0)*EV + c] = a0;
        outp[(rr0+rg+1)*EV + c] = a1;
        outp[(rr0+rg+2)*EV + c] = a2;
        outp[(rr0+rg+3)*EV + c] = a3;
    }
}

// ---------------------------------------------------------------------------
// K2: masked-softmax attention. grid = B*H*8 (16-q tiles), 128 threads.
// out[b,h,q,d] = sum_k m[b,k,d]*e_k*v[b,k,d] / sum_k m[b,k,d]*e_k
// ---------------------------------------------------------------------------
__global__ void __launch_bounds__(128) attn_kernel(
    const float* __restrict__ value, const int* __restrict__ mask)
{
    __shared__ float qs[16*DKd];
    __shared__ float ks[SK*DKd];
    __shared__ float mv[SK*DIM];
    __shared__ float mf[SK*DIM];
    __shared__ float es[16*SK];

    int blk = blockIdx.x;
    int qg  = blk & 7;
    int h   = (blk >> 3) & 7;
    int b   = blk >> 6;
    int q0  = qg * 16;
    int t   = threadIdx.x;

    qs[t] = g_q[(b*SQ + q0 + (t>>3))*EV + h*DKd + (t&7)];
    #pragma unroll
    for (int j = 0; j < 8; j++) {
        int idx = t + j*128;
        ks[idx] = g_k[(b*SK + (idx>>3))*EV + h*DKd + (idx&7)];
    }
    {
        const float4* v4 = (const float4*)(value + b*SK*DIM);
        const int4*   m4 = (const int4*)  (mask  + b*SK*DIM);
        float4* mv4 = (float4*)mv;
        float4* mf4 = (float4*)mf;
        #pragma unroll
        for (int j = 0; j < 8; j++) {
            int idx = t + j*128;
            int4 mm = m4[idx]; float4 vv = v4[idx];
            float4 av, af;
            av.x = mm.x ? vv.x : 0.f;  af.x = mm.x ? 1.f : 0.f;
            av.y = mm.y ? vv.y : 0.f;  af.y = mm.y ? 1.f : 0.f;
            av.z = mm.z ? vv.z : 0.f;  af.z = mm.z ? 1.f : 0.f;
            av.w = mm.w ? vv.w : 0.f;  af.w = mm.w ? 1.f : 0.f;
            mv4[idx] = av; mf4[idx] = af;
        }
    }
    __syncthreads();

    const float scale = 0.35355339059327373f;   // 1/sqrt(8)

    // phase A: scores + softmax weights
    {
        int q  = t >> 3;
        int kq = t & 7;
        float qr[DKd];
        #pragma unroll
        for (int j = 0; j < DKd; j++) qr[j] = qs[q*DKd + j];

        float s[16];
        int kbase = kq * 16;
        #pragma unroll
        for (int i = 0; i < 16; i++) {
            const float4* kp = (const float4*)&ks[(kbase+i)*DKd];
            float4 k0 = kp[0], k1 = kp[1];
            float acc = qr[0]*k0.x;
            acc = fmaf(qr[1], k0.y, acc);
            acc = fmaf(qr[2], k0.z, acc);
            acc = fmaf(qr[3], k0.w, acc);
            acc = fmaf(qr[4], k1.x, acc);
            acc = fmaf(qr[5], k1.y, acc);
            acc = fmaf(qr[6], k1.z, acc);
            acc = fmaf(qr[7], k1.w, acc);
            s[i] = acc;
        }
        float mx = s[0];
        #pragma unroll
        for (int i = 1; i < 16; i++) mx = fmaxf(mx, s[i]);
        mx = fmaxf(mx, __shfl_xor_sync(0xffffffff, mx, 1));
        mx = fmaxf(mx, __shfl_xor_sync(0xffffffff, mx, 2));
        mx = fmaxf(mx, __shfl_xor_sync(0xffffffff, mx, 4));
        float msc = mx * scale;
        #pragma unroll
        for (int i = 0; i < 16; i++)
            es[q*SK + kbase + i] = __expf(fmaf(s[i], scale, -msc));
    }
    __syncthreads();

    // phase B: masked weighted accumulation
    {
        int q  = t >> 3;
        int dq = t & 7;
        float n0=0.f, n1=0.f, n2=0.f, n3=0.f;
        float d0=0.f, d1=0.f, d2=0.f, d3=0.f;
        const float4* mv4 = (const float4*)mv;
        const float4* mf4 = (const float4*)mf;
        const float4* ep4 = (const float4*)&es[q*SK];
        #pragma unroll 4
        for (int k4 = 0; k4 < SK/4; k4++) {
            float4 e4 = ep4[k4];
            #pragma unroll
            for (int j = 0; j < 4; j++) {
                float e = (j==0) ? e4.x : (j==1) ? e4.y : (j==2) ? e4.z : e4.w;
                int k = k4*4 + j;
                float4 v = mv4[k*8 + dq];
                float4 m = mf4[k*8 + dq];
                n0 = fmaf(e, v.x, n0);  d0 = fmaf(e, m.x, d0);
                n1 = fmaf(e, v.y, n1);  d1 = fmaf(e, m.y, d1);
                n2 = fmaf(e, v.z, n2);  d2 = fmaf(e, m.z, d2);
                n3 = fmaf(e, v.w, n3);  d3 = fmaf(e, m.w, d3);
            }
        }
        float4 o;
        o.x = __fdividef(n0, d0); o.y = __fdividef(n1, d1);
        o.z = __fdividef(n2, d2); o.w = __fdividef(n3, d3);
        *(float4*)&g_x[(b*SQ + q0 + q)*(Hh*DIM) + h*DIM + dq*4] = o;
    }
}

// ---------------------------------------------------------------------------
// K3 (256 threads):
//   blocks [0,128):   y = x@wo + bo, 8 rows/block, 2-seg p-split
//   blocks [128,256): impute MLP, 8 rows/block
// ---------------------------------------------------------------------------
__global__ void __launch_bounds__(256) fused3_kernel(
    const float* __restrict__ wo, const float* __restrict__ bo,
    const float* __restrict__ imp,
    const float* __restrict__ wd1, const float* __restrict__ bd1,
    const float* __restrict__ lng, const float* __restrict__ lnb,
    const float* __restrict__ wd2, const float* __restrict__ bd2,
    float* __restrict__ y_out, float* __restrict__ qd_out)
{
    __shared__ __align__(16) float smem[3072];   // 12KB, reused per branch
    int t = threadIdx.x;

    if (blockIdx.x < 128) {
        // ---------------- out GEMM ----------------
        float* xt  = smem;            // [256][8] transposed, 8KB
        float* red = smem + 2048;     // 4KB partials

        int row0 = blockIdx.x * 8;
        #pragma unroll
        for (int j = 0; j < 8; j++) {
            int idx = t + j*256;      // 0..2047
            int r = idx >> 8, p = idx & 255;
            xt[p*8 + r] = g_x[row0*256 + idx];
        }
        __syncthreads();

        int c   = t & 127;
        int seg = t >> 7;             // 0..1, p range [seg*128, seg*128+128)
        int p0  = seg * 128;

        float acc[8];
        #pragma unroll
        for (int r = 0; r < 8; r++) acc[r] = 0.f;

        const float4* x4 = (const float4*)xt;
        #pragma unroll 8
        for (int pi = 0; pi < 128; pi++) {
            int p = p0 + pi;
            float w = wo[p*NH + c];
            float4 a = x4[p*2], b = x4[p*2+1];
            acc[0] = fmaf(a.x, w, acc[0]);
            acc[1] = fmaf(a.y, w, acc[1]);
            acc[2] = fmaf(a.z, w, acc[2]);
            acc[3] = fmaf(a.w, w, acc[3]);
            acc[4] = fmaf(b.x, w, acc[4]);
            acc[5] = fmaf(b.y, w, acc[5]);
            acc[6] = fmaf(b.z, w, acc[6]);
            acc[7] = fmaf(b.w, w, acc[7]);
        }
        if (seg == 1) {
            #pragma unroll
            for (int r = 0; r < 8; r++) red[r*128 + c] = acc[r];
        }
        __syncthreads();
        if (seg == 0) {
            float bb = bo[c];
            #pragma unroll
            for (int r = 0; r < 8; r++)
                y_out[(row0+r)*NH + c] = acc[r] + bb + red[r*128 + c];
        }
    } else {
        // ---------------- impute MLP (8 rows/block) ----------------
        float* xi   = smem;            // [8][16] 128 f
        float* htm  = smem + 128;      // [128][8] transposed, 1024 f
        float* redS = smem + 1152;     // 32 f
        float* redQ = smem + 1184;     // 32 f

        int row0 = (blockIdx.x - 128) * 8;
        if (t < 128) xi[t] = imp[row0*16 + t];
        __syncthreads();

        int c1   = t & 127;
        int base = (t >> 7) * 4;       // rows base..base+3
        int w8   = t >> 5;             // warp 0..7
        int lane = t & 31;

        float a[4];
        {
            float bb = bd1[c1];
            #pragma unroll
            for (int j = 0; j < 4; j++) a[j] = bb;
            #pragma unroll
            for (int i = 0; i < 16; i++) {
                float w = wd1[i*NH + c1];
                #pragma unroll
                for (int j = 0; j < 4; j++)
                    a[j] = fmaf(xi[(base+j)*16 + i], w, a[j]);
            }
        }

        float ss[4], qq[4];
        #pragma unroll
        for (int j = 0; j < 4; j++) { ss[j] = a[j]; qq[j] = a[j]*a[j]; }
        #pragma unroll
        for (int off = 16; off > 0; off >>= 1) {
            #pragma unroll
            for (int j = 0; j < 4; j++) {
                ss[j] += __shfl_xor_sync(0xffffffff, ss[j], off);
                qq[j] += __shfl_xor_sync(0xffffffff, qq[j], off);
            }
        }
        if (lane == 0) {
            #pragma unroll
            for (int j = 0; j < 4; j++) { redS[w8*4+j] = ss[j]; redQ[w8*4+j] = qq[j]; }
        }
        __syncthreads();

        float g = lng[c1], be = lnb[c1];
        int gw = (base == 0) ? 0 : 4;      // contributing warp group
        {
            float4 hv;
            float* hp = (float*)&hv;
            #pragma unroll
            for (int j = 0; j < 4; j++) {
                float S = redS[(gw+0)*4+j] + redS[(gw+1)*4+j]
                        + redS[(gw+2)*4+j] + redS[(gw+3)*4+j];
                float Q = redQ[(gw+0)*4+j] + redQ[(gw+1)*4+j]
                        + redQ[(gw+2)*4+j] + redQ[(gw+3)*4+j];
                float mu  = S * (1.f/128.f);
                float var = Q * (1.f/128.f) - mu*mu;
                float ln = (a[j] - mu) * rsqrtf(var + 1e-5f) * g + be;
                hp[j] = fmaxf(ln, 0.f);
            }
            *(float4*)&htm[c1*8 + base] = hv;
        }
        __syncthreads();

        float acc[4];
        {
            float bb = bd2[c1];
            #pragma unroll
            for (int j = 0; j < 4; j++) acc[j] = bb;
            #pragma unroll 8
            for (int p = 0; p < NH; p++) {
                float w = wd2[p*NH + c1];
                float4 h = *(const float4*)&htm[p*8 + base];
                acc[0] = fmaf(h.x, w, acc[0]);
                acc[1] = fmaf(h.y, w, acc[1]);
                acc[2] = fmaf(h.z, w, acc[2]);
                acc[3] = fmaf(h.w, w, acc[3]);
            }
        }
        #pragma unroll
        for (int j = 0; j < 4; j++)
            qd_out[(row0+base+j)*NH + c1] = acc[j];
    }
}

// ---------------------------------------------------------------------------
extern "C" void kernel_launch(void* const* d_in, const int* in_sizes, int n_in,
                              void* d_out, int out_size)
{
    bool dictOrder = (in_sizes[4] == Bn*SK*DIM);

    const float *qv, *kv, *val, *imp, *w1, *b1, *w2, *wq, *bq, *wk, *bk,
                *wo, *bo, *wd1, *bd1, *lng, *lnb, *wd2, *bd2;
    const int* mask;

    if (dictOrder) {
        qv  = (const float*)d_in[0];  kv  = (const float*)d_in[1];
        val = (const float*)d_in[2];  imp = (const float*)d_in[3];
        mask= (const int*)  d_in[4];
        w1  = (const float*)d_in[5];  b1  = (const float*)d_in[6];
        w2  = (const float*)d_in[7];
        wq  = (const float*)d_in[8];  bq  = (const float*)d_in[9];
        wk  = (const float*)d_in[10]; bk  = (const float*)d_in[11];
        wo  = (const float*)d_in[12]; bo  = (const float*)d_in[13];
        wd1 = (const float*)d_in[14]; bd1 = (const float*)d_in[15];
        lng = (const float*)d_in[16]; lnb = (const float*)d_in[17];
        wd2 = (const float*)d_in[18]; bd2 = (const float*)d_in[19];
    } else {
        qv  = (const float*)d_in[0];  kv  = (const float*)d_in[1];
        val = (const float*)d_in[2];  imp = (const float*)d_in[3];
        w1  = (const float*)d_in[4];  b1  = (const float*)d_in[5];
        w2  = (const float*)d_in[6];
        wq  = (const float*)d_in[7];  bq  = (const float*)d_in[8];
        wk  = (const float*)d_in[9];  bk  = (const float*)d_in[10];
        wo  = (const float*)d_in[11]; bo  = (const float*)d_in[12];
        wd1 = (const float*)d_in[13]; bd1 = (const float*)d_in[14];
        lng = (const float*)d_in[15]; lnb = (const float*)d_in[16];
        wd2 = (const float*)d_in[17]; bd2 = (const float*)d_in[18];
        mask= (const int*)  d_in[19];
    }

    float* y  = (float*)d_out;                       // [8,128,128]
    float* qd = (float*)d_out + Bn*SQ*NH;            // [8,128,128]

    proj_kernel<<<128, 256>>>(qv, kv, w1, b1, w2, wq, bq, wk, bk);
    attn_kernel<<<Bn*Hh*8, 128>>>(val, mask);
    fused3_kernel<<<256, 256>>>(wo, bo, imp, wd1, bd1, lng, lnb, wd2, bd2,
                                y, qd);
}